// round 6
// baseline (speedup 1.0000x reference)
#include <cuda_runtime.h>
#include <math_constants.h>

#define N_MAX 30720
#define M_MAX 7680
#define KNN_K 16
#define TILE_PTS 2048

__device__ float4 g_pos4[N_MAX];
__device__ int    g_nbr[M_MAX * KNN_K];

union F2U { unsigned long long u; float2 f; };

__device__ __forceinline__ void ffma2(unsigned long long& d,
                                      unsigned long long a,
                                      unsigned long long b) {
    asm("fma.rn.f32x2 %0, %1, %2, %0;" : "+l"(d) : "l"(a), "l"(b));
}
__device__ __forceinline__ unsigned long long dup2(float x) {
    unsigned long long r;
    asm("mov.b64 %0, {%1, %1};" : "=l"(r) : "f"(x));
    return r;
}

// ---------------------------------------------------------------------------
// Kernel 0: pack pos -> float4 with precomputed squared norm
// ---------------------------------------------------------------------------
__global__ void pack_pos_kernel(const float* __restrict__ pos, int N) {
    int i = blockIdx.x * blockDim.x + threadIdx.x;
    if (i < N) {
        float x = pos[3 * i + 0];
        float y = pos[3 * i + 1];
        float z = pos[3 * i + 2];
        g_pos4[i] = make_float4(x, y, z, x * x + y * y + z * z);
    }
}

// ---------------------------------------------------------------------------
// Warp-collective sorted-list insert. List lives in lanes [lo, lo+16).
// ---------------------------------------------------------------------------
__device__ __forceinline__ void insert_list(float& d, int gid,
                                            float& lv, int& li,
                                            float& th, int lane, int lo)
{
    const unsigned FULL = 0xFFFFFFFFu;
    while (true) {
        unsigned mk = __ballot_sync(FULL, d < th);
        if (!mk) break;
        int b = __ffs(mk) - 1;
        float v  = __shfl_sync(FULL, d, b);
        int   vi = __shfl_sync(FULL, gid, b);
        float up  = __shfl_up_sync(FULL, lv, 1);
        int   upi = __shfl_up_sync(FULL, li, 1);
        if ((lane >= lo) && (lane < lo + 16) && (v < lv)) {
            bool pg = (lane > lo) && (v < up);
            lv = pg ? up  : v;
            li = pg ? upi : vi;
        }
        th = __shfl_sync(FULL, lv, lo + 15);
        if (lane == b) d = CUDART_INF_F;
    }
}

// ---------------------------------------------------------------------------
// Kernel 1: brute-force KNN. SoA smem tile, packed f32x2 distances,
// 4 points per lane per iteration, warp-collective top-16.
// Key: d' = pw - 2*q.p  (== d2 - |q|^2, same ordering).
// ---------------------------------------------------------------------------
__global__ __launch_bounds__(256) void knn_kernel(
    const float* __restrict__ pos, const int* __restrict__ idx, int N, int M)
{
    __shared__ float s_px[TILE_PTS];
    __shared__ float s_py[TILE_PTS];
    __shared__ float s_pz[TILE_PTS];
    __shared__ float s_pw[TILE_PTS];
    const unsigned FULL = 0xFFFFFFFFu;
    int tid  = threadIdx.x;
    int lane = tid & 31;
    int wid  = tid >> 5;

    int q0 = blockIdx.x * 16 + wid * 2;
    int q1 = q0 + 1;
    bool vA = (q0 < M);
    bool vB = (q1 < M);

    float qAx = 0.f, qAy = 0.f, qAz = 0.f;
    float qBx = 0.f, qBy = 0.f, qBz = 0.f;
    if (vA) { int p = idx[q0]; qAx = pos[3*p]; qAy = pos[3*p+1]; qAz = pos[3*p+2]; }
    if (vB) { int p = idx[q1]; qBx = pos[3*p]; qBy = pos[3*p+1]; qBz = pos[3*p+2]; }

    unsigned long long tAx = dup2(-2.f * qAx), tAy = dup2(-2.f * qAy), tAz = dup2(-2.f * qAz);
    unsigned long long tBx = dup2(-2.f * qBx), tBy = dup2(-2.f * qBy), tBz = dup2(-2.f * qBz);

    float lv = CUDART_INF_F;
    int   li = 0;
    float thA = vA ? CUDART_INF_F : -CUDART_INF_F;
    float thB = vB ? CUDART_INF_F : -CUDART_INF_F;

    for (int base = 0; base < N; base += TILE_PTS) {
        __syncthreads();
        for (int i = tid; i < TILE_PTS; i += 256) {
            int g = base + i;
            float4 f = (g < N) ? g_pos4[g]
                               : make_float4(0.f, 0.f, 0.f, CUDART_INF_F);
            s_px[i] = f.x; s_py[i] = f.y; s_pz[i] = f.z; s_pw[i] = f.w;
        }
        __syncthreads();

        for (int p0 = lane * 4; p0 < TILE_PTS; p0 += 128) {
            ulonglong2 xq = *(const ulonglong2*)&s_px[p0];
            ulonglong2 yq = *(const ulonglong2*)&s_py[p0];
            ulonglong2 zq = *(const ulonglong2*)&s_pz[p0];
            ulonglong2 wq = *(const ulonglong2*)&s_pw[p0];

            F2U a01, a23, b01, b23;
            a01.u = wq.x; ffma2(a01.u, xq.x, tAx); ffma2(a01.u, yq.x, tAy); ffma2(a01.u, zq.x, tAz);
            a23.u = wq.y; ffma2(a23.u, xq.y, tAx); ffma2(a23.u, yq.y, tAy); ffma2(a23.u, zq.y, tAz);
            b01.u = wq.x; ffma2(b01.u, xq.x, tBx); ffma2(b01.u, yq.x, tBy); ffma2(b01.u, zq.x, tBz);
            b23.u = wq.y; ffma2(b23.u, xq.y, tBx); ffma2(b23.u, yq.y, tBy); ffma2(b23.u, zq.y, tBz);

            float mA = fminf(fminf(a01.f.x, a01.f.y), fminf(a23.f.x, a23.f.y));
            float mB = fminf(fminf(b01.f.x, b01.f.y), fminf(b23.f.x, b23.f.y));
            bool cand = (mA < thA) | (mB < thB);
            if (__any_sync(FULL, cand)) {
                int g0 = base + p0;
                insert_list(a01.f.x, g0,     lv, li, thA, lane, 0);
                insert_list(a01.f.y, g0 + 1, lv, li, thA, lane, 0);
                insert_list(a23.f.x, g0 + 2, lv, li, thA, lane, 0);
                insert_list(a23.f.y, g0 + 3, lv, li, thA, lane, 0);
                insert_list(b01.f.x, g0,     lv, li, thB, lane, 16);
                insert_list(b01.f.y, g0 + 1, lv, li, thB, lane, 16);
                insert_list(b23.f.x, g0 + 2, lv, li, thB, lane, 16);
                insert_list(b23.f.y, g0 + 3, lv, li, thB, lane, 16);
            }
        }
    }

    if (vA && lane < 16)  g_nbr[q0 * KNN_K + lane]        = li;
    if (vB && lane >= 16) g_nbr[q1 * KNN_K + (lane - 16)] = li;
}

// ---------------------------------------------------------------------------
// Kernel 2: fused LocSE MLP + attentive pooling + global MLP.
// Block = 128 threads = 4 warps; one warp per query.
// fij stored pair-major: s_f[w][rp*256 + k*2 + (r&1)] = fij[2*rp+(r&1)][k]
// Attention GEMM uses packed fma.rn.f32x2 (row-pairs in one b64 reg),
// a-operand loaded as LDS.128 covering two consecutive k.
// ---------------------------------------------------------------------------
__global__ __launch_bounds__(128) void fuse_kernel(
    const float* __restrict__ x,     const float* __restrict__ pos,
    const int*   __restrict__ idx,
    const float* __restrict__ W_pos, const float* __restrict__ b_pos,
    const float* __restrict__ W_att, const float* __restrict__ b_att,
    const float* __restrict__ W_glob,const float* __restrict__ b_glob,
    float* __restrict__ out, int M)
{
    __shared__ __align__(16) float s_f[4][8 * 128 * 2];   // 32 KB pair-major fij
    __shared__ __align__(16) float s_wt[16 * 128];        //  8 KB streamed W tile
    __shared__ float s_wpos[10][64];                      // 2.5 KB
    __shared__ __align__(16) float s_aggr[4][128];        //  2 KB

    const unsigned FULL = 0xFFFFFFFFu;
    int tid  = threadIdx.x;
    int lane = tid & 31;
    int w    = tid >> 5;
    int m    = blockIdx.x * 4 + w;
    bool valid = (m < M);

    for (int i = tid; i < 640; i += 128) ((float*)s_wpos)[i] = W_pos[i];

    // --- rel features + x gather (pair-major writes) ---
    float rel[10] = {0,0,0,0,0,0,0,0,0,0};
    int nj = 0;
    if (valid) {
        int qi = idx[m];
        float pix = pos[3*qi], piy = pos[3*qi+1], piz = pos[3*qi+2];
        if (lane < KNN_K) {
            nj = g_nbr[m * KNN_K + lane];
            float pjx = pos[3*nj], pjy = pos[3*nj+1], pjz = pos[3*nj+2];
            float vx = pix - pjx, vy = piy - pjy, vz = piz - pjz;
            float dd = sqrtf(vx*vx + vy*vy + vz*vz);
            rel[0]=pix; rel[1]=piy; rel[2]=piz;
            rel[3]=pjx; rel[4]=pjy; rel[5]=pjz;
            rel[6]=vx;  rel[7]=vy;  rel[8]=vz;  rel[9]=dd;
        }
        #pragma unroll
        for (int jj = 0; jj < KNN_K; jj++) {
            int n2 = __shfl_sync(FULL, nj, jj);
            float2 v = *(const float2*)(x + (size_t)n2 * 64 + lane * 2);
            int base = (jj >> 1) * 256 + (jj & 1);
            s_f[w][base + 4 * lane]     = v.x;   // k = 2*lane
            s_f[w][base + 4 * lane + 2] = v.y;   // k = 2*lane+1
        }
    }
    __syncthreads();  // s_wpos ready

    // --- pos MLP -> fij cols 64..127 ---
    if (valid) {
        float bp0 = b_pos[lane], bp1 = b_pos[lane + 32];
        #pragma unroll
        for (int jj = 0; jj < KNN_K; jj++) {
            float rv[10];
            #pragma unroll
            for (int t = 0; t < 10; t++) rv[t] = __shfl_sync(FULL, rel[t], jj);
            float a0 = bp0, a1 = bp1;
            #pragma unroll
            for (int t = 0; t < 10; t++) {
                a0 = fmaf(rv[t], s_wpos[t][lane],      a0);
                a1 = fmaf(rv[t], s_wpos[t][lane + 32], a1);
            }
            int base = (jj >> 1) * 256 + (jj & 1);
            s_f[w][base + (64 + lane) * 2] = fmaxf(a0, 0.f);
            s_f[w][base + (96 + lane) * 2] = fmaxf(a1, 0.f);
        }
    }

    // --- attention GEMM: g = fij @ W_att + b_att (packed f32x2) ---
    int col = lane * 4;
    F2U acc[32];   // acc[rp*4+u]: lo=row 2rp, hi=row 2rp+1, col=col+u
    {
        float4 bat = valid ? *(const float4*)(b_att + col) : make_float4(0,0,0,0);
        float bb[4] = {bat.x, bat.y, bat.z, bat.w};
        #pragma unroll
        for (int rp = 0; rp < 8; rp++)
            #pragma unroll
            for (int u = 0; u < 4; u++)
                acc[rp*4+u].f = make_float2(bb[u], bb[u]);
    }
    #pragma unroll 1
    for (int t = 0; t < 8; t++) {
        __syncthreads();
        const float4* src = (const float4*)(W_att + t * 16 * 128);
        #pragma unroll
        for (int u = 0; u < 4; u++)
            ((float4*)s_wt)[u * 128 + tid] = src[u * 128 + tid];
        __syncthreads();
        if (valid) {
            #pragma unroll
            for (int kk = 0; kk < 16; kk += 2) {
                float4 wa = *(const float4*)&s_wt[kk * 128 + col];
                float4 wb = *(const float4*)&s_wt[(kk + 1) * 128 + col];
                unsigned long long wa0 = dup2(wa.x), wa1 = dup2(wa.y);
                unsigned long long wa2 = dup2(wa.z), wa3 = dup2(wa.w);
                unsigned long long wb0 = dup2(wb.x), wb1 = dup2(wb.y);
                unsigned long long wb2 = dup2(wb.z), wb3 = dup2(wb.w);
                int kf = (t * 16 + kk) * 2;
                #pragma unroll
                for (int rp = 0; rp < 8; rp++) {
                    ulonglong2 ap =
                        *(const ulonglong2*)&s_f[w][rp * 256 + kf];
                    ffma2(acc[rp*4+0].u, ap.x, wa0);
                    ffma2(acc[rp*4+1].u, ap.x, wa1);
                    ffma2(acc[rp*4+2].u, ap.x, wa2);
                    ffma2(acc[rp*4+3].u, ap.x, wa3);
                    ffma2(acc[rp*4+0].u, ap.y, wb0);
                    ffma2(acc[rp*4+1].u, ap.y, wb1);
                    ffma2(acc[rp*4+2].u, ap.y, wb2);
                    ffma2(acc[rp*4+3].u, ap.y, wb3);
                }
            }
        }
    }

    // --- softmax over feature dim + weighted mean over K ---
    float ag[4] = {0.f, 0.f, 0.f, 0.f};
    if (valid) {
        #pragma unroll
        for (int r = 0; r < 16; r++) {
            int rp = r >> 1, h = r & 1;
            float v0 = h ? acc[rp*4+0].f.y : acc[rp*4+0].f.x;
            float v1 = h ? acc[rp*4+1].f.y : acc[rp*4+1].f.x;
            float v2 = h ? acc[rp*4+2].f.y : acc[rp*4+2].f.x;
            float v3 = h ? acc[rp*4+3].f.y : acc[rp*4+3].f.x;
            float mx = fmaxf(fmaxf(v0, v1), fmaxf(v2, v3));
            #pragma unroll
            for (int o = 16; o > 0; o >>= 1)
                mx = fmaxf(mx, __shfl_xor_sync(FULL, mx, o));
            float e0 = __expf(v0 - mx);
            float e1 = __expf(v1 - mx);
            float e2 = __expf(v2 - mx);
            float e3 = __expf(v3 - mx);
            float sm = (e0 + e1) + (e2 + e3);
            #pragma unroll
            for (int o = 16; o > 0; o >>= 1)
                sm += __shfl_xor_sync(FULL, sm, o);
            float inv = 1.0f / sm;
            int fb = rp * 256 + h;
            ag[0] = fmaf(e0 * inv, s_f[w][fb + (col + 0) * 2], ag[0]);
            ag[1] = fmaf(e1 * inv, s_f[w][fb + (col + 1) * 2], ag[1]);
            ag[2] = fmaf(e2 * inv, s_f[w][fb + (col + 2) * 2], ag[2]);
            ag[3] = fmaf(e3 * inv, s_f[w][fb + (col + 3) * 2], ag[3]);
        }
        const float s16 = 1.0f / 16.0f;
        float4 agv = make_float4(ag[0]*s16, ag[1]*s16, ag[2]*s16, ag[3]*s16);
        *(float4*)&s_aggr[w][col] = agv;
    }

    // --- global MLP: out = relu(aggr @ W_glob + b_glob) (packed) ---
    F2U o01, o23;
    {
        float4 bg = valid ? *(const float4*)(b_glob + col) : make_float4(0,0,0,0);
        o01.f = make_float2(bg.x, bg.y);
        o23.f = make_float2(bg.z, bg.w);
    }
    #pragma unroll 1
    for (int t = 0; t < 8; t++) {
        __syncthreads();
        const float4* src = (const float4*)(W_glob + t * 16 * 128);
        #pragma unroll
        for (int u = 0; u < 4; u++)
            ((float4*)s_wt)[u * 128 + tid] = src[u * 128 + tid];
        __syncthreads();
        if (valid) {
            #pragma unroll
            for (int kk = 0; kk < 16; kk++) {
                float4 w4 = *(const float4*)&s_wt[kk * 128 + col];
                F2U p01, p23;
                p01.f = make_float2(w4.x, w4.y);
                p23.f = make_float2(w4.z, w4.w);
                unsigned long long aa = dup2(s_aggr[w][t * 16 + kk]);
                ffma2(o01.u, aa, p01.u);
                ffma2(o23.u, aa, p23.u);
            }
        }
    }
    if (valid) {
        float4 o4 = make_float4(fmaxf(o01.f.x, 0.f), fmaxf(o01.f.y, 0.f),
                                fmaxf(o23.f.x, 0.f), fmaxf(o23.f.y, 0.f));
        *(float4*)(out + (size_t)m * 128 + col) = o4;
    }
}

// ---------------------------------------------------------------------------
// Launch
// ---------------------------------------------------------------------------
extern "C" void kernel_launch(void* const* d_in, const int* in_sizes, int n_in,
                              void* d_out, int out_size)
{
    const float* x      = (const float*)d_in[0];
    const float* pos    = (const float*)d_in[1];
    const int*   idx    = (const int*)  d_in[2];
    const float* W_pos  = (const float*)d_in[3];
    const float* b_pos  = (const float*)d_in[4];
    const float* W_att  = (const float*)d_in[5];
    const float* b_att  = (const float*)d_in[6];
    const float* W_glob = (const float*)d_in[7];
    const float* b_glob = (const float*)d_in[8];
    float* out = (float*)d_out;

    int N = in_sizes[1] / 3;   // 30000
    int M = in_sizes[2];       // 7500
    if (N > N_MAX) N = N_MAX;
    if (M > M_MAX) M = M_MAX;

    pack_pos_kernel<<<(N + 255) / 256, 256>>>(pos, N);
    knn_kernel<<<(M + 15) / 16, 256>>>(pos, idx, N, M);
    fuse_kernel<<<(M + 3) / 4, 128>>>(x, pos, idx, W_pos, b_pos,
                                      W_att, b_att, W_glob, b_glob, out, M);
}

// round 7
// speedup vs baseline: 1.0012x; 1.0012x over previous
#include <cuda_runtime.h>
#include <math_constants.h>

#define N_MAX 30720
#define M_MAX 7680
#define KNN_K 16
#define TILE_PTS 2048

__device__ float4 g_pos4[N_MAX];
__device__ int    g_nbr[M_MAX * KNN_K];

union F2U { unsigned long long u; float2 f; };

__device__ __forceinline__ void ffma2(unsigned long long& d,
                                      unsigned long long a,
                                      unsigned long long b) {
    asm("fma.rn.f32x2 %0, %1, %2, %0;" : "+l"(d) : "l"(a), "l"(b));
}
__device__ __forceinline__ unsigned long long dup2(float x) {
    unsigned long long r;
    asm("mov.b64 %0, {%1, %1};" : "=l"(r) : "f"(x));
    return r;
}

// ---------------------------------------------------------------------------
// Kernel 0: pack pos -> float4 with precomputed squared norm
// ---------------------------------------------------------------------------
__global__ void pack_pos_kernel(const float* __restrict__ pos, int N) {
    int i = blockIdx.x * blockDim.x + threadIdx.x;
    if (i < N) {
        float x = pos[3 * i + 0];
        float y = pos[3 * i + 1];
        float z = pos[3 * i + 2];
        g_pos4[i] = make_float4(x, y, z, x * x + y * y + z * z);
    }
}

// ---------------------------------------------------------------------------
// Warp-collective sorted-list insert. List lives in lanes [lo, lo+16).
// ---------------------------------------------------------------------------
__device__ __forceinline__ void insert_list(float& d, int gid,
                                            float& lv, int& li,
                                            float& th, int lane, int lo)
{
    const unsigned FULL = 0xFFFFFFFFu;
    while (true) {
        unsigned mk = __ballot_sync(FULL, d < th);
        if (!mk) break;
        int b = __ffs(mk) - 1;
        float v  = __shfl_sync(FULL, d, b);
        int   vi = __shfl_sync(FULL, gid, b);
        float up  = __shfl_up_sync(FULL, lv, 1);
        int   upi = __shfl_up_sync(FULL, li, 1);
        if ((lane >= lo) && (lane < lo + 16) && (v < lv)) {
            bool pg = (lane > lo) && (v < up);
            lv = pg ? up  : v;
            li = pg ? upi : vi;
        }
        th = __shfl_sync(FULL, lv, lo + 15);
        if (lane == b) d = CUDART_INF_F;
    }
}

// ---------------------------------------------------------------------------
// Kernel 1: brute-force KNN. SoA smem tile, packed f32x2 distances,
// 4 points per lane per iteration, warp-collective top-16.
// Key: d' = pw - 2*q.p  (== d2 - |q|^2, same ordering).
// ---------------------------------------------------------------------------
__global__ __launch_bounds__(256) void knn_kernel(
    const float* __restrict__ pos, const int* __restrict__ idx, int N, int M)
{
    __shared__ float s_px[TILE_PTS];
    __shared__ float s_py[TILE_PTS];
    __shared__ float s_pz[TILE_PTS];
    __shared__ float s_pw[TILE_PTS];
    const unsigned FULL = 0xFFFFFFFFu;
    int tid  = threadIdx.x;
    int lane = tid & 31;
    int wid  = tid >> 5;

    int q0 = blockIdx.x * 16 + wid * 2;
    int q1 = q0 + 1;
    bool vA = (q0 < M);
    bool vB = (q1 < M);

    float qAx = 0.f, qAy = 0.f, qAz = 0.f;
    float qBx = 0.f, qBy = 0.f, qBz = 0.f;
    if (vA) { int p = idx[q0]; qAx = pos[3*p]; qAy = pos[3*p+1]; qAz = pos[3*p+2]; }
    if (vB) { int p = idx[q1]; qBx = pos[3*p]; qBy = pos[3*p+1]; qBz = pos[3*p+2]; }

    unsigned long long tAx = dup2(-2.f * qAx), tAy = dup2(-2.f * qAy), tAz = dup2(-2.f * qAz);
    unsigned long long tBx = dup2(-2.f * qBx), tBy = dup2(-2.f * qBy), tBz = dup2(-2.f * qBz);

    float lv = CUDART_INF_F;
    int   li = 0;
    float thA = vA ? CUDART_INF_F : -CUDART_INF_F;
    float thB = vB ? CUDART_INF_F : -CUDART_INF_F;

    for (int base = 0; base < N; base += TILE_PTS) {
        __syncthreads();
        for (int i = tid; i < TILE_PTS; i += 256) {
            int g = base + i;
            float4 f = (g < N) ? g_pos4[g]
                               : make_float4(0.f, 0.f, 0.f, CUDART_INF_F);
            s_px[i] = f.x; s_py[i] = f.y; s_pz[i] = f.z; s_pw[i] = f.w;
        }
        __syncthreads();

        for (int p0 = lane * 4; p0 < TILE_PTS; p0 += 128) {
            ulonglong2 xq = *(const ulonglong2*)&s_px[p0];
            ulonglong2 yq = *(const ulonglong2*)&s_py[p0];
            ulonglong2 zq = *(const ulonglong2*)&s_pz[p0];
            ulonglong2 wq = *(const ulonglong2*)&s_pw[p0];

            F2U a01, a23, b01, b23;
            a01.u = wq.x; ffma2(a01.u, xq.x, tAx); ffma2(a01.u, yq.x, tAy); ffma2(a01.u, zq.x, tAz);
            a23.u = wq.y; ffma2(a23.u, xq.y, tAx); ffma2(a23.u, yq.y, tAy); ffma2(a23.u, zq.y, tAz);
            b01.u = wq.x; ffma2(b01.u, xq.x, tBx); ffma2(b01.u, yq.x, tBy); ffma2(b01.u, zq.x, tBz);
            b23.u = wq.y; ffma2(b23.u, xq.y, tBx); ffma2(b23.u, yq.y, tBy); ffma2(b23.u, zq.y, tBz);

            float mA = fminf(fminf(a01.f.x, a01.f.y), fminf(a23.f.x, a23.f.y));
            float mB = fminf(fminf(b01.f.x, b01.f.y), fminf(b23.f.x, b23.f.y));
            bool cand = (mA < thA) | (mB < thB);
            if (__any_sync(FULL, cand)) {
                int g0 = base + p0;
                insert_list(a01.f.x, g0,     lv, li, thA, lane, 0);
                insert_list(a01.f.y, g0 + 1, lv, li, thA, lane, 0);
                insert_list(a23.f.x, g0 + 2, lv, li, thA, lane, 0);
                insert_list(a23.f.y, g0 + 3, lv, li, thA, lane, 0);
                insert_list(b01.f.x, g0,     lv, li, thB, lane, 16);
                insert_list(b01.f.y, g0 + 1, lv, li, thB, lane, 16);
                insert_list(b23.f.x, g0 + 2, lv, li, thB, lane, 16);
                insert_list(b23.f.y, g0 + 3, lv, li, thB, lane, 16);
            }
        }
    }

    if (vA && lane < 16)  g_nbr[q0 * KNN_K + lane]        = li;
    if (vB && lane >= 16) g_nbr[q1 * KNN_K + (lane - 16)] = li;
}

// ---------------------------------------------------------------------------
// Kernel 2: fused LocSE MLP + attentive pooling + global MLP.
// Block = 128 threads = 4 warps; one warp per query.
// fij stored pair-major: s_f[w][rp*256 + k*2 + (r&1)] = fij[2*rp+(r&1)][k]
// Attention GEMM uses packed fma.rn.f32x2 (row-pairs in one b64 reg),
// a-operand loaded as LDS.128 covering two consecutive k.
// ---------------------------------------------------------------------------
__global__ __launch_bounds__(128) void fuse_kernel(
    const float* __restrict__ x,     const float* __restrict__ pos,
    const int*   __restrict__ idx,
    const float* __restrict__ W_pos, const float* __restrict__ b_pos,
    const float* __restrict__ W_att, const float* __restrict__ b_att,
    const float* __restrict__ W_glob,const float* __restrict__ b_glob,
    float* __restrict__ out, int M)
{
    __shared__ __align__(16) float s_f[4][8 * 128 * 2];   // 32 KB pair-major fij
    __shared__ __align__(16) float s_wt[16 * 128];        //  8 KB streamed W tile
    __shared__ float s_wpos[10][64];                      // 2.5 KB
    __shared__ __align__(16) float s_aggr[4][128];        //  2 KB

    const unsigned FULL = 0xFFFFFFFFu;
    int tid  = threadIdx.x;
    int lane = tid & 31;
    int w    = tid >> 5;
    int m    = blockIdx.x * 4 + w;
    bool valid = (m < M);

    for (int i = tid; i < 640; i += 128) ((float*)s_wpos)[i] = W_pos[i];

    // --- rel features + x gather (pair-major writes) ---
    float rel[10] = {0,0,0,0,0,0,0,0,0,0};
    int nj = 0;
    if (valid) {
        int qi = idx[m];
        float pix = pos[3*qi], piy = pos[3*qi+1], piz = pos[3*qi+2];
        if (lane < KNN_K) {
            nj = g_nbr[m * KNN_K + lane];
            float pjx = pos[3*nj], pjy = pos[3*nj+1], pjz = pos[3*nj+2];
            float vx = pix - pjx, vy = piy - pjy, vz = piz - pjz;
            float dd = sqrtf(vx*vx + vy*vy + vz*vz);
            rel[0]=pix; rel[1]=piy; rel[2]=piz;
            rel[3]=pjx; rel[4]=pjy; rel[5]=pjz;
            rel[6]=vx;  rel[7]=vy;  rel[8]=vz;  rel[9]=dd;
        }
        #pragma unroll
        for (int jj = 0; jj < KNN_K; jj++) {
            int n2 = __shfl_sync(FULL, nj, jj);
            float2 v = *(const float2*)(x + (size_t)n2 * 64 + lane * 2);
            int base = (jj >> 1) * 256 + (jj & 1);
            s_f[w][base + 4 * lane]     = v.x;   // k = 2*lane
            s_f[w][base + 4 * lane + 2] = v.y;   // k = 2*lane+1
        }
    }
    __syncthreads();  // s_wpos ready

    // --- pos MLP -> fij cols 64..127 ---
    if (valid) {
        float bp0 = b_pos[lane], bp1 = b_pos[lane + 32];
        #pragma unroll
        for (int jj = 0; jj < KNN_K; jj++) {
            float rv[10];
            #pragma unroll
            for (int t = 0; t < 10; t++) rv[t] = __shfl_sync(FULL, rel[t], jj);
            float a0 = bp0, a1 = bp1;
            #pragma unroll
            for (int t = 0; t < 10; t++) {
                a0 = fmaf(rv[t], s_wpos[t][lane],      a0);
                a1 = fmaf(rv[t], s_wpos[t][lane + 32], a1);
            }
            int base = (jj >> 1) * 256 + (jj & 1);
            s_f[w][base + (64 + lane) * 2] = fmaxf(a0, 0.f);
            s_f[w][base + (96 + lane) * 2] = fmaxf(a1, 0.f);
        }
    }

    // --- attention GEMM: g = fij @ W_att + b_att (packed f32x2) ---
    int col = lane * 4;
    F2U acc[32];   // acc[rp*4+u]: lo=row 2rp, hi=row 2rp+1, col=col+u
    {
        float4 bat = valid ? *(const float4*)(b_att + col) : make_float4(0,0,0,0);
        float bb[4] = {bat.x, bat.y, bat.z, bat.w};
        #pragma unroll
        for (int rp = 0; rp < 8; rp++)
            #pragma unroll
            for (int u = 0; u < 4; u++)
                acc[rp*4+u].f = make_float2(bb[u], bb[u]);
    }
    #pragma unroll 1
    for (int t = 0; t < 8; t++) {
        __syncthreads();
        const float4* src = (const float4*)(W_att + t * 16 * 128);
        #pragma unroll
        for (int u = 0; u < 4; u++)
            ((float4*)s_wt)[u * 128 + tid] = src[u * 128 + tid];
        __syncthreads();
        if (valid) {
            #pragma unroll
            for (int kk = 0; kk < 16; kk += 2) {
                float4 wa = *(const float4*)&s_wt[kk * 128 + col];
                float4 wb = *(const float4*)&s_wt[(kk + 1) * 128 + col];
                unsigned long long wa0 = dup2(wa.x), wa1 = dup2(wa.y);
                unsigned long long wa2 = dup2(wa.z), wa3 = dup2(wa.w);
                unsigned long long wb0 = dup2(wb.x), wb1 = dup2(wb.y);
                unsigned long long wb2 = dup2(wb.z), wb3 = dup2(wb.w);
                int kf = (t * 16 + kk) * 2;
                #pragma unroll
                for (int rp = 0; rp < 8; rp++) {
                    ulonglong2 ap =
                        *(const ulonglong2*)&s_f[w][rp * 256 + kf];
                    ffma2(acc[rp*4+0].u, ap.x, wa0);
                    ffma2(acc[rp*4+1].u, ap.x, wa1);
                    ffma2(acc[rp*4+2].u, ap.x, wa2);
                    ffma2(acc[rp*4+3].u, ap.x, wa3);
                    ffma2(acc[rp*4+0].u, ap.y, wb0);
                    ffma2(acc[rp*4+1].u, ap.y, wb1);
                    ffma2(acc[rp*4+2].u, ap.y, wb2);
                    ffma2(acc[rp*4+3].u, ap.y, wb3);
                }
            }
        }
    }

    // --- softmax over feature dim + weighted mean over K ---
    float ag[4] = {0.f, 0.f, 0.f, 0.f};
    if (valid) {
        #pragma unroll
        for (int r = 0; r < 16; r++) {
            int rp = r >> 1, h = r & 1;
            float v0 = h ? acc[rp*4+0].f.y : acc[rp*4+0].f.x;
            float v1 = h ? acc[rp*4+1].f.y : acc[rp*4+1].f.x;
            float v2 = h ? acc[rp*4+2].f.y : acc[rp*4+2].f.x;
            float v3 = h ? acc[rp*4+3].f.y : acc[rp*4+3].f.x;
            float mx = fmaxf(fmaxf(v0, v1), fmaxf(v2, v3));
            #pragma unroll
            for (int o = 16; o > 0; o >>= 1)
                mx = fmaxf(mx, __shfl_xor_sync(FULL, mx, o));
            float e0 = __expf(v0 - mx);
            float e1 = __expf(v1 - mx);
            float e2 = __expf(v2 - mx);
            float e3 = __expf(v3 - mx);
            float sm = (e0 + e1) + (e2 + e3);
            #pragma unroll
            for (int o = 16; o > 0; o >>= 1)
                sm += __shfl_xor_sync(FULL, sm, o);
            float inv = 1.0f / sm;
            int fb = rp * 256 + h;
            ag[0] = fmaf(e0 * inv, s_f[w][fb + (col + 0) * 2], ag[0]);
            ag[1] = fmaf(e1 * inv, s_f[w][fb + (col + 1) * 2], ag[1]);
            ag[2] = fmaf(e2 * inv, s_f[w][fb + (col + 2) * 2], ag[2]);
            ag[3] = fmaf(e3 * inv, s_f[w][fb + (col + 3) * 2], ag[3]);
        }
        const float s16 = 1.0f / 16.0f;
        float4 agv = make_float4(ag[0]*s16, ag[1]*s16, ag[2]*s16, ag[3]*s16);
        *(float4*)&s_aggr[w][col] = agv;
    }

    // --- global MLP: out = relu(aggr @ W_glob + b_glob) (packed) ---
    F2U o01, o23;
    {
        float4 bg = valid ? *(const float4*)(b_glob + col) : make_float4(0,0,0,0);
        o01.f = make_float2(bg.x, bg.y);
        o23.f = make_float2(bg.z, bg.w);
    }
    #pragma unroll 1
    for (int t = 0; t < 8; t++) {
        __syncthreads();
        const float4* src = (const float4*)(W_glob + t * 16 * 128);
        #pragma unroll
        for (int u = 0; u < 4; u++)
            ((float4*)s_wt)[u * 128 + tid] = src[u * 128 + tid];
        __syncthreads();
        if (valid) {
            #pragma unroll
            for (int kk = 0; kk < 16; kk++) {
                float4 w4 = *(const float4*)&s_wt[kk * 128 + col];
                F2U p01, p23;
                p01.f = make_float2(w4.x, w4.y);
                p23.f = make_float2(w4.z, w4.w);
                unsigned long long aa = dup2(s_aggr[w][t * 16 + kk]);
                ffma2(o01.u, aa, p01.u);
                ffma2(o23.u, aa, p23.u);
            }
        }
    }
    if (valid) {
        float4 o4 = make_float4(fmaxf(o01.f.x, 0.f), fmaxf(o01.f.y, 0.f),
                                fmaxf(o23.f.x, 0.f), fmaxf(o23.f.y, 0.f));
        *(float4*)(out + (size_t)m * 128 + col) = o4;
    }
}

// ---------------------------------------------------------------------------
// Launch
// ---------------------------------------------------------------------------
extern "C" void kernel_launch(void* const* d_in, const int* in_sizes, int n_in,
                              void* d_out, int out_size)
{
    const float* x      = (const float*)d_in[0];
    const float* pos    = (const float*)d_in[1];
    const int*   idx    = (const int*)  d_in[2];
    const float* W_pos  = (const float*)d_in[3];
    const float* b_pos  = (const float*)d_in[4];
    const float* W_att  = (const float*)d_in[5];
    const float* b_att  = (const float*)d_in[6];
    const float* W_glob = (const float*)d_in[7];
    const float* b_glob = (const float*)d_in[8];
    float* out = (float*)d_out;

    int N = in_sizes[1] / 3;   // 30000
    int M = in_sizes[2];       // 7500
    if (N > N_MAX) N = N_MAX;
    if (M > M_MAX) M = M_MAX;

    pack_pos_kernel<<<(N + 255) / 256, 256>>>(pos, N);
    knn_kernel<<<(M + 15) / 16, 256>>>(pos, idx, N, M);
    fuse_kernel<<<(M + 3) / 4, 128>>>(x, pos, idx, W_pos, b_pos,
                                      W_att, b_att, W_glob, b_glob, out, M);
}